// round 10
// baseline (speedup 1.0000x reference)
#include <cuda_runtime.h>
#include <cstdint>

#define BATCH 32
#define CIN   256
#define HW    3136          // 56*56
#define HWH   1568          // HW/2
#define CR    8
#define NPIX  (BATCH*HW)    // 100352
#define NPAIR (NPIX/2)      // 50176
#define COUT  44            // 8 + 36

#define KS    4             // K-splits
#define CPK   (CIN/KS)      // 64 channels per split
#define PRB   64            // pairs per block (256 thr = 64 pairs * 4 ks)
#define PSTR  9             // padded partial row stride (u64)

// z buffer, pixel-major: [b][p][c], 32B per pixel record
__device__ float g_z[NPIX*CR];

typedef unsigned long long u64;

__device__ __forceinline__ u64 fma2(u64 a, u64 b, u64 c) {
    u64 d;
    asm("fma.rn.f32x2 %0, %1, %2, %3;" : "=l"(d) : "l"(a), "l"(b), "l"(c));
    return d;
}
__device__ __forceinline__ u64 add2(u64 a, u64 b) {
    u64 d;
    asm("add.rn.f32x2 %0, %1, %2;" : "=l"(d) : "l"(a), "l"(b));
    return d;
}
__device__ __forceinline__ u64 pack2(float lo, float hi) {
    u64 r;
    asm("mov.b64 %0, {%1, %2};" : "=l"(r) : "f"(lo), "f"(hi));
    return r;
}
__device__ __forceinline__ float2 unpack2(u64 v) {
    float2 r;
    asm("mov.b64 {%0, %1}, %2;" : "=f"(r.x), "=f"(r.y) : "l"(v));
    return r;
}

// ============================================================
// 1x1 conv + BN(folded) + ReLU. 2 px/thread, KS=4.
// 4-slot x 4-channel register pipeline: 3 load-groups always in
// flight per thread. smem = union(weights, partials) = 18.4 KB.
// grid = NPAIR/64 = 784 blocks x 256 threads.
// ============================================================
__global__ void __launch_bounds__(256) conv1x1_k(const float* __restrict__ x,
                                                 const float* __restrict__ wr,
                                                 const float* __restrict__ gamma,
                                                 const float* __restrict__ beta,
                                                 const float* __restrict__ mean,
                                                 const float* __restrict__ var) {
    __shared__ __align__(16) u64 su[4*PRB*PSTR];   // 18.4 KB union (>=2048 u64)
    __shared__ float sinv[CR], sbias[CR];

    u64* sw = su;                        // weights occupy first 2048 u64
    int tid = threadIdx.x;

    if (tid < CR) {
        int c = tid;
        float inv = gamma[c] * rsqrtf(var[c] + 1e-5f);
        sinv[c]  = inv;
        sbias[c] = beta[c] - mean[c] * inv;
    }
    __syncthreads();
    #pragma unroll
    for (int i = tid; i < CIN*CR; i += 256) {
        int ci = i >> 3;
        int c  = i & 7;
        float wgt = wr[c*CIN + ci] * sinv[c];
        sw[i] = pack2(wgt, wgt);
    }
    __syncthreads();

    int lp = tid & (PRB-1);              // pair within block
    int ks = tid >> 6;                   // k-split 0..3
    int pp = blockIdx.x * PRB + lp;      // global pair
    int b  = pp / HWH;
    int pi = pp - b*HWH;

    const u64* xp = reinterpret_cast<const u64*>(x)
                  + (size_t)(b*CIN + ks*CPK)*HWH + pi;
    const u64* swb = &sw[ks*CPK*CR];

    u64 acc[CR];
    #pragma unroll
    for (int c = 0; c < CR; c++) acc[c] = 0ull;

    // 16 groups of 4 channels; 4 slots, load group g+3 before computing g
    u64 xs[4][4];
    #pragma unroll
    for (int g0 = 0; g0 < 3; g0++)
        #pragma unroll
        for (int u = 0; u < 4; u++)
            xs[g0][u] = __ldg(&xp[(size_t)(g0*4+u)*HWH]);

    #pragma unroll
    for (int g = 0; g < 16; g++) {
        if (g + 3 < 16) {
            #pragma unroll
            for (int u = 0; u < 4; u++)
                xs[(g+3)&3][u] = __ldg(&xp[(size_t)((g+3)*4+u)*HWH]);
        }
        #pragma unroll
        for (int u = 0; u < 4; u++) {
            u64 xv = xs[g&3][u];
            const ulonglong2* wrow =
                reinterpret_cast<const ulonglong2*>(&swb[(g*4+u)*CR]);
            ulonglong2 w01 = wrow[0], w23 = wrow[1], w45 = wrow[2], w67 = wrow[3];
            acc[0] = fma2(w01.x, xv, acc[0]);
            acc[1] = fma2(w01.y, xv, acc[1]);
            acc[2] = fma2(w23.x, xv, acc[2]);
            acc[3] = fma2(w23.y, xv, acc[3]);
            acc[4] = fma2(w45.x, xv, acc[4]);
            acc[5] = fma2(w45.y, xv, acc[5]);
            acc[6] = fma2(w67.x, xv, acc[6]);
            acc[7] = fma2(w67.y, xv, acc[7]);
        }
    }

    __syncthreads();                     // weights no longer needed

    // partials: row per (ks, pair), padded stride 9
    {
        u64* row = &su[(size_t)(ks*PRB + lp)*PSTR];
        #pragma unroll
        for (int c = 0; c < CR; c++) row[c] = acc[c];
    }
    __syncthreads();

    // reduce: thread t -> pair pr2 = t>>2, channel-pair g = t&3
    {
        int pr2 = tid >> 2;
        int g   = tid & 3;
        u64 s0 = 0ull, s1 = 0ull;
        #pragma unroll
        for (int k = 0; k < KS; k++) {
            const u64* row = &su[(size_t)(k*PRB + pr2)*PSTR + 2*g];
            s0 = add2(s0, row[0]);
            s1 = add2(s1, row[1]);
        }
        float2 v0 = unpack2(s0);         // ch 2g   : (px0, px1)
        float2 v1 = unpack2(s1);         // ch 2g+1 : (px0, px1)
        float b0 = sbias[2*g], b1 = sbias[2*g+1];
        float a0 = fmaxf(v0.x + b0, 0.f), a1 = fmaxf(v1.x + b1, 0.f);
        float c0 = fmaxf(v0.y + b0, 0.f), c1 = fmaxf(v1.y + b1, 0.f);
        int pp2 = blockIdx.x*PRB + pr2;
        int b2  = pp2 / HWH;
        int pi2 = pp2 - b2*HWH;
        int px0 = 2*pi2;
        float2* z0 = reinterpret_cast<float2*>(g_z + ((size_t)b2*HW + px0)*CR + 2*g);
        float2* z1 = reinterpret_cast<float2*>(g_z + ((size_t)b2*HW + px0 + 1)*CR + 2*g);
        *z0 = make_float2(a0, a1);
        *z1 = make_float2(c0, c1);
    }
}

// ============================================================
// Depthwise 3x3 (scale folded) + L2-norms + pairwise products.
// R7 version (best measured): halo-padded planes, unconditional
// LDS.128 taps. grid = 448 blocks of 224 threads.
// ============================================================
#define TW 58
__global__ void __launch_bounds__(224) twist_k(float* __restrict__ out,
                                               const float* __restrict__ wdw,
                                               const float* __restrict__ scale) {
    __shared__ float4 sA[6*TW];
    __shared__ float4 sC[6*TW];
    __shared__ float  swd[CR*9];

    int tid = threadIdx.x;
    if (tid < CR*9) swd[tid] = wdw[tid] * scale[tid/9];

    int b    = blockIdx.x / 14;
    int band = blockIdx.x - b*14;
    int y0   = band * 4;

    const float4* zb = reinterpret_cast<const float4*>(g_z) + (size_t)b*HW*2;

    for (int f = tid; f < 6*TW; f += 224) {
        int r  = f / TW;
        int c  = f - r*TW;
        int gy = y0 + r - 1;
        int gx = c - 1;
        float4 va = make_float4(0.f,0.f,0.f,0.f);
        float4 vc = va;
        if ((unsigned)gy < 56u && (unsigned)gx < 56u) {
            size_t q = (size_t)(gy*56 + gx)*2;
            va = __ldg(&zb[q]);
            vc = __ldg(&zb[q+1]);
        }
        sA[f] = va;
        sC[f] = vc;
    }
    __syncthreads();

    int row = tid / 56;                 // 0..3
    int col = tid - row*56;             // 0..55
    int s0  = (row+1)*TW + (col+1);     // center index

    float zc[CR], t[CR];
    {
        float4 a = sA[s0];
        float4 c = sC[s0];
        zc[0]=a.x; zc[1]=a.y; zc[2]=a.z; zc[3]=a.w;
        zc[4]=c.x; zc[5]=c.y; zc[6]=c.z; zc[7]=c.w;
    }
    #pragma unroll
    for (int c = 0; c < CR; c++) t[c] = 0.f;

    #pragma unroll
    for (int dy = -1; dy <= 1; dy++) {
        #pragma unroll
        for (int dx = -1; dx <= 1; dx++) {
            int si = s0 + dy*TW + dx;
            int k  = (dy+1)*3 + (dx+1);
            float4 a = sA[si];
            float4 c = sC[si];
            t[0] = fmaf(a.x, swd[0*9+k], t[0]);
            t[1] = fmaf(a.y, swd[1*9+k], t[1]);
            t[2] = fmaf(a.z, swd[2*9+k], t[2]);
            t[3] = fmaf(a.w, swd[3*9+k], t[3]);
            t[4] = fmaf(c.x, swd[4*9+k], t[4]);
            t[5] = fmaf(c.y, swd[5*9+k], t[5]);
            t[6] = fmaf(c.z, swd[6*9+k], t[6]);
            t[7] = fmaf(c.w, swd[7*9+k], t[7]);
        }
    }

    float s2z = 0.f, s2t = 0.f;
    #pragma unroll
    for (int c = 0; c < CR; c++) { s2z = fmaf(zc[c], zc[c], s2z); s2t = fmaf(t[c], t[c], s2t); }
    float iz = 1.0f / fmaxf(sqrtf(s2z), 1e-6f);
    float it = 1.0f / fmaxf(sqrtf(s2t), 1e-6f);

    float zn[CR], tn[CR];
    #pragma unroll
    for (int c = 0; c < CR; c++) { zn[c] = zc[c]*iz; tn[c] = t[c]*it; }

    int p = (y0 + row)*56 + col;
    float* ob = out + (size_t)b*COUT*HW + p;
    #pragma unroll
    for (int c = 0; c < CR; c++) ob[(size_t)c*HW] = zn[c];

    int k = 8;
    #pragma unroll
    for (int i = 0; i < CR; i++) {
        #pragma unroll
        for (int j = i; j < CR; j++) {
            ob[(size_t)k*HW] = zn[i]*tn[j];
            k++;
        }
    }
}

// ============================================================
extern "C" void kernel_launch(void* const* d_in, const int* in_sizes, int n_in,
                              void* d_out, int out_size) {
    const float* x     = (const float*)d_in[0];
    const float* wr    = (const float*)d_in[1];
    const float* gamma = (const float*)d_in[2];
    const float* beta  = (const float*)d_in[3];
    const float* mean  = (const float*)d_in[4];
    const float* var   = (const float*)d_in[5];
    const float* wdw   = (const float*)d_in[6];
    const float* scale = (const float*)d_in[7];
    float* out = (float*)d_out;

    conv1x1_k<<<NPAIR/PRB, 256>>>(x, wr, gamma, beta, mean, var);
    twist_k<<<BATCH*14, 224>>>(out, wdw, scale);
}